// round 1
// baseline (speedup 1.0000x reference)
#include <cuda_runtime.h>

// ---------------------------------------------------------------------------
// Attention_18476949308128 — fp32 baseline
// B=2, S=2048, D_EMBED=D_MODEL=1024, H=16, d_k=64
// Pipeline: QKV proj (NT+bias) -> scores (NT, batched bh) -> softmax rows
//           -> attn@V (NN, batched bh) -> out proj (NT+bias)
// ---------------------------------------------------------------------------

#define TILE 64
#define BK   16

// Scratch (static __device__ globals: allocation-free per harness rules)
__device__ float g_Q[4096 * 1024];
__device__ float g_K[4096 * 1024];
__device__ float g_V[4096 * 1024];
__device__ float g_C[4096 * 1024];          // concat/blended, [b, q, h, d]
__device__ float g_attn[134217728];          // [b, h, q, k] fp32 (512 MB)

// C[m,n] = sum_k A[m*lda+k] * B[n*ldb+k] (+ bias[n])
// blockIdx.z encodes (b,h): offsets = b*Sb + h*Sh per operand.
__global__ __launch_bounds__(256) void gemm_nt(
    const float* __restrict__ A, const float* __restrict__ B,
    float* __restrict__ C, const float* __restrict__ bias,
    int M, int N, int K, int lda, int ldb, int ldc,
    long aSb, long aSh, long bSb, long bSh, long cSb, long cSh)
{
    long bb = blockIdx.z >> 4, hh = blockIdx.z & 15;
    A += bb * aSb + hh * aSh;
    B += bb * bSb + hh * bSh;
    C += bb * cSb + hh * cSh;

    __shared__ float As[BK][TILE + 4];
    __shared__ float Bs[BK][TILE + 4];

    int t    = threadIdx.x;            // 256 threads
    int m0   = blockIdx.y * TILE;
    int n0   = blockIdx.x * TILE;
    int lrow = t >> 2;                 // 0..63
    int lq   = (t & 3) << 2;           // 0,4,8,12 (k quad)
    int tm   = (t >> 4) << 2;          // 0..60
    int tn   = (t & 15) << 2;          // 0..60

    float acc[4][4] = {};

    for (int k0 = 0; k0 < K; k0 += BK) {
        float4 av = *(const float4*)(A + (long)(m0 + lrow) * lda + k0 + lq);
        float4 bv = *(const float4*)(B + (long)(n0 + lrow) * ldb + k0 + lq);
        As[lq + 0][lrow] = av.x; As[lq + 1][lrow] = av.y;
        As[lq + 2][lrow] = av.z; As[lq + 3][lrow] = av.w;
        Bs[lq + 0][lrow] = bv.x; Bs[lq + 1][lrow] = bv.y;
        Bs[lq + 2][lrow] = bv.z; Bs[lq + 3][lrow] = bv.w;
        __syncthreads();
#pragma unroll
        for (int k = 0; k < BK; k++) {
            float4 a = *(const float4*)&As[k][tm];
            float4 b = *(const float4*)&Bs[k][tn];
            acc[0][0] += a.x * b.x; acc[0][1] += a.x * b.y;
            acc[0][2] += a.x * b.z; acc[0][3] += a.x * b.w;
            acc[1][0] += a.y * b.x; acc[1][1] += a.y * b.y;
            acc[1][2] += a.y * b.z; acc[1][3] += a.y * b.w;
            acc[2][0] += a.z * b.x; acc[2][1] += a.z * b.y;
            acc[2][2] += a.z * b.z; acc[2][3] += a.z * b.w;
            acc[3][0] += a.w * b.x; acc[3][1] += a.w * b.y;
            acc[3][2] += a.w * b.z; acc[3][3] += a.w * b.w;
        }
        __syncthreads();
    }

    float4 bvec;
    if (bias) {
        bvec = *(const float4*)(bias + n0 + tn);
    } else {
        bvec.x = bvec.y = bvec.z = bvec.w = 0.f;
    }
#pragma unroll
    for (int i = 0; i < 4; i++) {
        float4 v;
        v.x = acc[i][0] + bvec.x;
        v.y = acc[i][1] + bvec.y;
        v.z = acc[i][2] + bvec.z;
        v.w = acc[i][3] + bvec.w;
        *(float4*)(C + (long)(m0 + tm + i) * ldc + n0 + tn) = v;
    }
}

// C[m,n] = sum_k A[m*lda+k] * B[k*ldb+n]   (NN form, for attn @ V)
__global__ __launch_bounds__(256) void gemm_nn(
    const float* __restrict__ A, const float* __restrict__ B,
    float* __restrict__ C,
    int M, int N, int K, int lda, int ldb, int ldc,
    long aSb, long aSh, long bSb, long bSh, long cSb, long cSh)
{
    long bb = blockIdx.z >> 4, hh = blockIdx.z & 15;
    A += bb * aSb + hh * aSh;
    B += bb * bSb + hh * bSh;
    C += bb * cSb + hh * cSh;

    __shared__ float As[BK][TILE + 4];
    __shared__ float Bs[BK][TILE + 4];

    int t    = threadIdx.x;
    int m0   = blockIdx.y * TILE;
    int n0   = blockIdx.x * TILE;
    int lrow = t >> 2;
    int lq   = (t & 3) << 2;
    int bkr  = t >> 4;                 // 0..15 (k row of B tile)
    int bnq  = (t & 15) << 2;          // 0..60 (n quad)
    int tm   = (t >> 4) << 2;
    int tn   = (t & 15) << 2;

    float acc[4][4] = {};

    for (int k0 = 0; k0 < K; k0 += BK) {
        float4 av = *(const float4*)(A + (long)(m0 + lrow) * lda + k0 + lq);
        float4 bv = *(const float4*)(B + (long)(k0 + bkr) * ldb + n0 + bnq);
        As[lq + 0][lrow] = av.x; As[lq + 1][lrow] = av.y;
        As[lq + 2][lrow] = av.z; As[lq + 3][lrow] = av.w;
        *(float4*)&Bs[bkr][bnq] = bv;
        __syncthreads();
#pragma unroll
        for (int k = 0; k < BK; k++) {
            float4 a = *(const float4*)&As[k][tm];
            float4 b = *(const float4*)&Bs[k][tn];
            acc[0][0] += a.x * b.x; acc[0][1] += a.x * b.y;
            acc[0][2] += a.x * b.z; acc[0][3] += a.x * b.w;
            acc[1][0] += a.y * b.x; acc[1][1] += a.y * b.y;
            acc[1][2] += a.y * b.z; acc[1][3] += a.y * b.w;
            acc[2][0] += a.z * b.x; acc[2][1] += a.z * b.y;
            acc[2][2] += a.z * b.z; acc[2][3] += a.z * b.w;
            acc[3][0] += a.w * b.x; acc[3][1] += a.w * b.y;
            acc[3][2] += a.w * b.z; acc[3][3] += a.w * b.w;
        }
        __syncthreads();
    }

#pragma unroll
    for (int i = 0; i < 4; i++) {
        float4 v;
        v.x = acc[i][0]; v.y = acc[i][1]; v.z = acc[i][2]; v.w = acc[i][3];
        *(float4*)(C + (long)(m0 + tm + i) * ldc + n0 + tn) = v;
    }
}

// In-place masked softmax over rows of 2048. Row index = ((b*16+h)*2048 + q).
__global__ __launch_bounds__(256) void softmax_rows(
    float* __restrict__ attn, const float* __restrict__ mask)
{
    long row = blockIdx.x;                 // 0..65535
    int  b   = (int)(row >> 15);           // row / (16*2048)
    float* p = attn + row * 2048;
    const float* mrow = mask + (long)b * 2048;

    int t = threadIdx.x;
    float v[8];
    float mx = -1e30f;
#pragma unroll
    for (int i = 0; i < 8; i++) {
        int idx = t + i * 256;
        float s = p[idx] + (1.0f - mrow[idx]) * (-1e9f);
        v[i] = s;
        mx = fmaxf(mx, s);
    }
#pragma unroll
    for (int o = 16; o; o >>= 1) mx = fmaxf(mx, __shfl_xor_sync(0xffffffffu, mx, o));

    __shared__ float sm[8];
    if ((t & 31) == 0) sm[t >> 5] = mx;
    __syncthreads();
    float m = sm[0];
#pragma unroll
    for (int w = 1; w < 8; w++) m = fmaxf(m, sm[w]);
    __syncthreads();

    float sum = 0.f;
#pragma unroll
    for (int i = 0; i < 8; i++) {
        v[i] = __expf(v[i] - m);
        sum += v[i];
    }
#pragma unroll
    for (int o = 16; o; o >>= 1) sum += __shfl_xor_sync(0xffffffffu, sum, o);
    if ((t & 31) == 0) sm[t >> 5] = sum;
    __syncthreads();
    float tot = 0.f;
#pragma unroll
    for (int w = 0; w < 8; w++) tot += sm[w];
    float inv = 1.0f / tot;
#pragma unroll
    for (int i = 0; i < 8; i++) p[t + i * 256] = v[i] * inv;
}

extern "C" void kernel_launch(void* const* d_in, const int* in_sizes, int n_in,
                              void* d_out, int out_size)
{
    (void)in_sizes; (void)n_in;
    const float* query        = (const float*)d_in[0];
    const float* input_embeds = (const float*)d_in[1];
    const float* mask         = (const float*)d_in[2];
    const float* wq_w = (const float*)d_in[3];
    const float* wq_b = (const float*)d_in[4];
    const float* wk_w = (const float*)d_in[5];
    const float* wk_b = (const float*)d_in[6];
    const float* wv_w = (const float*)d_in[7];
    const float* wv_b = (const float*)d_in[8];
    const float* wo_w = (const float*)d_in[9];
    const float* wo_b = (const float*)d_in[10];
    float* out = (float*)d_out;

    float *Q, *K, *V, *Cc, *attn_scratch;
    cudaGetSymbolAddress((void**)&Q,  g_Q);
    cudaGetSymbolAddress((void**)&K,  g_K);
    cudaGetSymbolAddress((void**)&V,  g_V);
    cudaGetSymbolAddress((void**)&Cc, g_C);
    cudaGetSymbolAddress((void**)&attn_scratch, g_attn);

    const long OUT_E  = 4194304L;    // 2*2048*1024
    const long ATTN_E = 134217728L;  // 2*16*2048*2048
    float* attn = ((long)out_size >= OUT_E + ATTN_E) ? (out + OUT_E) : attn_scratch;

    dim3 blk(256);

    // 1) Projections: [4096,1024] = X[4096,1024] @ W^T[1024,1024] + b
    dim3 gProj(1024 / TILE, 4096 / TILE, 1);
    gemm_nt<<<gProj, blk>>>(query,        wq_w, Q, wq_b, 4096, 1024, 1024,
                            1024, 1024, 1024, 0, 0, 0, 0, 0, 0);
    gemm_nt<<<gProj, blk>>>(input_embeds, wk_w, K, wk_b, 4096, 1024, 1024,
                            1024, 1024, 1024, 0, 0, 0, 0, 0, 0);
    gemm_nt<<<gProj, blk>>>(input_embeds, wv_w, V, wv_b, 4096, 1024, 1024,
                            1024, 1024, 1024, 0, 0, 0, 0, 0, 0);

    // 2) scores[b,h,q,k] = Qh[2048,64] @ Kh^T  (batched over 32 bh)
    dim3 gS(2048 / TILE, 2048 / TILE, 32);
    gemm_nt<<<gS, blk>>>(Q, K, attn, nullptr, 2048, 2048, 64,
                         1024, 1024, 2048,
                         2048L * 1024, 64,              // A offsets (b,h)
                         2048L * 1024, 64,              // B offsets
                         16L * 2048 * 2048, 2048L * 2048); // C offsets

    // 3) softmax rows (+mask), in place
    softmax_rows<<<65536, blk>>>(attn, mask);

    // 4) blended[b,q,h,d] = attn @ Vh   (NN, batched over 32 bh)
    dim3 gAV(1, 2048 / TILE, 32);
    gemm_nn<<<gAV, blk>>>(attn, V, Cc, 2048, 64, 2048,
                          2048, 1024, 1024,
                          16L * 2048 * 2048, 2048L * 2048,
                          2048L * 1024, 64,
                          2048L * 1024, 64);

    // 5) out = concat @ wo^T + wo_b
    gemm_nt<<<gProj, blk>>>(Cc, wo_w, out, wo_b, 4096, 1024, 1024,
                            1024, 1024, 1024, 0, 0, 0, 0, 0, 0);
}